// round 2
// baseline (speedup 1.0000x reference)
#include <cuda_runtime.h>
#include <math.h>

#define NA 48            // atoms per molecule (fixed by problem)
#define NS 4             // species
#define NSHFR 16
#define NSHFA 4
#define NSHFZ 8
#define RAD_FEAT (NS * NSHFR)              // 64
#define ANG_SUB (NSHFA * NSHFZ)            // 32
#define NPAIRS_SP (NS * (NS + 1) / 2)      // 10
#define AEV_LEN (RAD_FEAT + NPAIRS_SP * ANG_SUB)  // 384
#define RCR_F 5.2f
#define RCA_F 3.5f
#define PI_F 3.14159265358979323846f

__device__ __forceinline__ int triu_idx(int a, int b) {
    int lo = min(a, b), hi = max(a, b);
    return lo * NS - (lo * (lo - 1)) / 2 + (hi - lo);
}

__device__ __forceinline__ float pow_zeta(float x, float zeta, bool z32) {
    if (z32) {
        // x^32 via 5 squarings
        float y = x * x;   // ^2
        y = y * y;         // ^4
        y = y * y;         // ^8
        y = y * y;         // ^16
        return y * y;      // ^32
    }
    return __powf(x, zeta);
}

__global__ __launch_bounds__(128, 8)
void aev_kernel(const float* __restrict__ coords,   // (M, A, 3)
                const float* __restrict__ gEtaR,    // (1,)
                const float* __restrict__ gShfR,    // (16,)
                const float* __restrict__ gEtaA,    // (1,)
                const float* __restrict__ gZeta,    // (1,)
                const float* __restrict__ gShfA,    // (4,)
                const float* __restrict__ gShfZ,    // (8,)
                const int*   __restrict__ species,  // (M, A)
                float* __restrict__ out)            // (M, A, 384)
{
    const int i = blockIdx.x;   // atom index within molecule
    const int m = blockIdx.y;   // molecule index
    const int tid = threadIdx.x;
    const int nthr = blockDim.x;

    __shared__ float sx[NA], sy[NA], sz[NA];
    __shared__ int   ssp[NA];
    __shared__ float shfr[NSHFR], shfa[NSHFA];
    __shared__ float cshfz[NSHFZ], sshfz[NSHFZ];
    __shared__ float s_etaR, s_etaA, s_zeta;
    __shared__ float aev[AEV_LEN];
    // compacted neighbor list (within RCA) for the angular part
    __shared__ float nvx[NA], nvy[NA], nvz[NA], nd[NA], nfc[NA];
    __shared__ int   nsp[NA];
    __shared__ int   ncount;

    // ---- load molecule data + params into SMEM, zero accumulators ----
    if (tid < NA) {
        const float* c = coords + ((size_t)m * NA + tid) * 3;
        sx[tid] = c[0];
        sy[tid] = c[1];
        sz[tid] = c[2];
        ssp[tid] = species[(size_t)m * NA + tid];
    }
    if (tid < NSHFR) shfr[tid] = gShfR[tid];
    if (tid < NSHFA) shfa[tid] = gShfA[tid];
    if (tid < NSHFZ) {
        float z = gShfZ[tid];
        cshfz[tid] = cosf(z);   // once per CTA; full precision
        sshfz[tid] = sinf(z);
    }
    if (tid == 0) {
        s_etaR = gEtaR[0];
        s_etaA = gEtaA[0];
        s_zeta = gZeta[0];
        ncount = 0;
    }
    for (int c = tid; c < AEV_LEN; c += nthr) aev[c] = 0.0f;
    __syncthreads();

    const float cx = sx[i], cy = sy[i], cz = sz[i];
    const float etaR = s_etaR, etaA = s_etaA, zeta = s_zeta;
    const bool z32 = (zeta == 32.0f);

    // ---- radial part + neighbor compaction ----
    for (int j = tid; j < NA; j += nthr) {
        if (j == i) continue;
        float dx = sx[j] - cx;
        float dy = sy[j] - cy;
        float dz = sz[j] - cz;
        float d = sqrtf(dx * dx + dy * dy + dz * dz);
        if (d <= RCR_F) {
            float fc = 0.5f * __cosf(d * (PI_F / RCR_F)) + 0.5f;
            float qfc = 0.25f * fc;
            int base = ssp[j] * NSHFR;
            #pragma unroll
            for (int k = 0; k < NSHFR; k++) {
                float t = d - shfr[k];
                float v = qfc * __expf(-etaR * t * t);
                atomicAdd(&aev[base + k], v);
            }
        }
        if (d <= RCA_F) {
            int slot = atomicAdd(&ncount, 1);
            nvx[slot] = dx;
            nvy[slot] = dy;
            nvz[slot] = dz;
            nd[slot]  = d;
            nfc[slot] = 0.5f * __cosf(d * (PI_F / RCA_F)) + 0.5f;
            nsp[slot] = ssp[j];
        }
    }
    __syncthreads();

    // ---- angular part: all unordered pairs of in-cutoff neighbors ----
    const int n = ncount;
    const int npairs = n * (n - 1) / 2;
    for (int p = tid; p < npairs; p += nthr) {
        // closed-form decode p -> (a, b), a < b  (n <= 48 so float sqrt is safe
        // with the fix-up below)
        float fn = (float)n;
        float disc = (2.0f * fn - 1.0f) * (2.0f * fn - 1.0f) - 8.0f * (float)p;
        int a = (int)((2.0f * fn - 1.0f - sqrtf(disc)) * 0.5f);
        // fix-up for float rounding
        while (a > 0 && p < a * n - (a * (a + 1)) / 2) a--;
        while (p >= (a + 1) * n - ((a + 1) * (a + 2)) / 2) a++;
        int b = p - (a * n - (a * (a + 1)) / 2) + a + 1;

        float d1 = nd[a], d2 = nd[b];
        float dot = nvx[a] * nvx[b] + nvy[a] * nvy[b] + nvz[a] * nvz[b];
        float cosv = 0.95f * dot / (fmaxf(d1, 1e-8f) * fmaxf(d2, 1e-8f));
        float sinv = sqrtf(fmaxf(1.0f - cosv * cosv, 0.0f));
        float dm = 0.5f * (d1 + d2);
        float fcj2 = 2.0f * nfc[a] * nfc[b];
        int base = RAD_FEAT + triu_idx(nsp[a], nsp[b]) * ANG_SUB;

        // f1[t] = ((1 + cos(ang - shfz_t))/2)^zeta * 2*fc1*fc2
        // with cos(ang - shfz_t) = cosv*cos(shfz_t) + sinv*sin(shfz_t)
        float f1[NSHFZ];
        #pragma unroll
        for (int t = 0; t < NSHFZ; t++) {
            float c = cosv * cshfz[t] + sinv * sshfz[t];
            float bse = 0.5f * (1.0f + c);
            f1[t] = pow_zeta(bse, zeta, z32) * fcj2;
        }
        #pragma unroll
        for (int s = 0; s < NSHFA; s++) {
            float dd = dm - shfa[s];
            float f2 = __expf(-etaA * dd * dd);
            #pragma unroll
            for (int t = 0; t < NSHFZ; t++) {
                atomicAdd(&aev[base + s * NSHFZ + t], f1[t] * f2);
            }
        }
    }
    __syncthreads();

    // ---- write out ----
    float* o = out + ((size_t)m * NA + i) * AEV_LEN;
    for (int c = tid; c < AEV_LEN; c += nthr) o[c] = aev[c];
}

extern "C" void kernel_launch(void* const* d_in, const int* in_sizes, int n_in,
                              void* d_out, int out_size) {
    const float* coords = (const float*)d_in[0];
    const float* EtaR   = (const float*)d_in[1];
    const float* ShfR   = (const float*)d_in[2];
    const float* EtaA   = (const float*)d_in[3];
    const float* Zeta   = (const float*)d_in[4];
    const float* ShfA   = (const float*)d_in[5];
    const float* ShfZ   = (const float*)d_in[6];
    const int*   spec   = (const int*)d_in[7];
    float* out = (float*)d_out;

    int MA = in_sizes[7];        // M * A
    int M = MA / NA;

    dim3 grid(NA, M);
    aev_kernel<<<grid, 128>>>(coords, EtaR, ShfR, EtaA, Zeta, ShfA, ShfZ, spec, out);
}

// round 3
// speedup vs baseline: 4.5909x; 4.5909x over previous
#include <cuda_runtime.h>
#include <math.h>

#define NA 48
#define NS 4
#define NSHFR 16
#define NSHFA 4
#define NSHFZ 8
#define RAD_FEAT (NS * NSHFR)                     // 64
#define ANG_SUB (NSHFA * NSHFZ)                   // 32
#define NPAIRS_SP (NS * (NS + 1) / 2)             // 10
#define ANG_FEAT (NPAIRS_SP * ANG_SUB)            // 320
#define AEV_LEN (RAD_FEAT + ANG_FEAT)             // 384
#define RCR_F 5.2f
#define RCA_F 3.5f
#define PI_F 3.14159265358979323846f
#define CHUNK 128

__device__ __forceinline__ int triu_idx(int a, int b) {
    int lo = min(a, b), hi = max(a, b);
    return lo * NS - (lo * (lo - 1)) / 2 + (hi - lo);
}

__device__ __forceinline__ float pow_zeta(float x, float zeta, bool z32) {
    if (z32) {
        float y = x * x;  // ^2
        y = y * y;        // ^4
        y = y * y;        // ^8
        y = y * y;        // ^16
        return y * y;     // ^32
    }
    return __powf(x, zeta);
}

__global__ __launch_bounds__(128, 8)
void aev_kernel(const float* __restrict__ coords,   // (M, A, 3)
                const float* __restrict__ gEtaR,
                const float* __restrict__ gShfR,    // (16,)
                const float* __restrict__ gEtaA,
                const float* __restrict__ gZeta,
                const float* __restrict__ gShfA,    // (4,)
                const float* __restrict__ gShfZ,    // (8,)
                const int*   __restrict__ species,  // (M, A)
                float* __restrict__ out)            // (M, A, 384)
{
    const int i = blockIdx.x;
    const int m = blockIdx.y;
    const int tid = threadIdx.x;
    const int lane = tid & 31;
    const int wid = tid >> 5;

    __shared__ float sx[NA], sy[NA], sz[NA];
    __shared__ int   ssp[NA];
    __shared__ float shfr[NSHFR], shfa[NSHFA];
    __shared__ float cshfz[NSHFZ], sshfz[NSHFZ];
    __shared__ float s_etaR, s_etaA, s_zeta;
    // radial neighbor list (d <= RCR)
    __shared__ float dR[NA], qfcR[NA];
    __shared__ int   spR[NA];
    // angular neighbor list (d <= RCA)
    __shared__ float avx[NA], avy[NA], avz[NA], ad[NA], afc[NA];
    __shared__ int   asp[NA];
    __shared__ int   wcntR[4], wcntA[4];
    // per-chunk pair data
    __shared__ float f1s[CHUNK * 9];   // padded stride 9
    __shared__ float f2s[CHUNK * 5];   // padded stride 5
    __shared__ int   ppidx[CHUNK];
    __shared__ float radout[RAD_FEAT];

    // ---- phase 0: load ----
    if (tid < NA) {
        const float* c = coords + ((size_t)m * NA + tid) * 3;
        sx[tid] = c[0];
        sy[tid] = c[1];
        sz[tid] = c[2];
        ssp[tid] = species[(size_t)m * NA + tid];
    }
    if (tid < NSHFR) shfr[tid] = gShfR[tid];
    if (tid < NSHFA) shfa[tid] = gShfA[tid];
    if (tid < NSHFZ) {
        float z = gShfZ[tid];
        cshfz[tid] = cosf(z);
        sshfz[tid] = sinf(z);
    }
    if (tid == 0) {
        s_etaR = gEtaR[0];
        s_etaA = gEtaA[0];
        s_zeta = gZeta[0];
    }
    if (tid < 4) { wcntR[tid] = 0; wcntA[tid] = 0; }
    __syncthreads();

    const float cx = sx[i], cy = sy[i], cz = sz[i];
    const float etaR = s_etaR, etaA = s_etaA, zeta = s_zeta;
    const bool z32 = (zeta == 32.0f);

    // ---- phase 1: deterministic neighbor compaction (warps 0,1 cover j=0..47) ----
    {
        int j = tid;
        float dx = 0.f, dy = 0.f, dz = 0.f, d = 1e9f;
        bool valid = (j < NA) && (j != i);
        if (valid) {
            dx = sx[j] - cx;
            dy = sy[j] - cy;
            dz = sz[j] - cz;
            d = sqrtf(dx * dx + dy * dy + dz * dz);
        }
        bool inR = valid && (d <= RCR_F);
        bool inA = valid && (d <= RCA_F);
        unsigned ballR = __ballot_sync(0xffffffffu, inR);
        unsigned ballA = __ballot_sync(0xffffffffu, inA);
        unsigned ltm = (1u << lane) - 1u;
        if (lane == 0 && wid < 4) {
            wcntR[wid] = __popc(ballR);
            wcntA[wid] = __popc(ballA);
        }
        __syncthreads();
        int offR = 0, offA = 0;
        for (int w = 0; w < wid; w++) { offR += wcntR[w]; offA += wcntA[w]; }
        if (inR) {
            int s = offR + __popc(ballR & ltm);
            dR[s] = d;
            qfcR[s] = 0.25f * (0.5f * __cosf(d * (PI_F / RCR_F)) + 0.5f);
            spR[s] = ssp[j];
        }
        if (inA) {
            int s = offA + __popc(ballA & ltm);
            avx[s] = dx; avy[s] = dy; avz[s] = dz;
            ad[s] = d;
            afc[s] = 0.5f * __cosf(d * (PI_F / RCA_F)) + 0.5f;
            asp[s] = ssp[j];
        }
    }
    __syncthreads();
    const int nR = wcntR[0] + wcntR[1] + wcntR[2] + wcntR[3];
    const int nA = wcntA[0] + wcntA[1] + wcntA[2] + wcntA[3];

    // ---- phase 2: radial, feature-parallel (threads 0..63 own (sp,k)) ----
    if (tid < RAD_FEAT) {
        int sp = tid >> 4;
        float sk = shfr[tid & 15];
        float acc = 0.0f;
        for (int j = 0; j < nR; j++) {
            if (spR[j] == sp) {
                float t = dR[j] - sk;
                acc += qfcR[j] * __expf(-etaR * t * t);
            }
        }
        radout[tid] = acc;
    }

    // ---- phase 3: angular pairs, chunked; feature accumulation in registers ----
    const int npairs = nA * (nA - 1) / 2;
    float acc0 = 0.f, acc1 = 0.f, acc2 = 0.f;

    for (int base = 0; base < npairs; base += CHUNK) {
        int p = base + tid;
        __syncthreads();   // protect previous chunk's reads before overwrite
        if (p < npairs) {
            // decode p -> (a,b), a<b
            int a = 0, rem = p;
            while (rem >= nA - 1 - a) { rem -= nA - 1 - a; a++; }
            int b = a + 1 + rem;

            float d1 = ad[a], d2 = ad[b];
            float dot = avx[a] * avx[b] + avy[a] * avy[b] + avz[a] * avz[b];
            float cosv = 0.95f * dot / (fmaxf(d1, 1e-8f) * fmaxf(d2, 1e-8f));
            float sinv = sqrtf(fmaxf(1.0f - cosv * cosv, 0.0f));
            float dm = 0.5f * (d1 + d2);
            float fcj2 = 2.0f * afc[a] * afc[b];
            ppidx[tid] = triu_idx(asp[a], asp[b]);

            #pragma unroll
            for (int t = 0; t < NSHFZ; t++) {
                float c = cosv * cshfz[t] + sinv * sshfz[t];
                float bse = 0.5f * (1.0f + c);
                f1s[tid * 9 + t] = pow_zeta(bse, zeta, z32) * fcj2;
            }
            #pragma unroll
            for (int s = 0; s < NSHFA; s++) {
                float dd = dm - shfa[s];
                f2s[tid * 5 + s] = __expf(-etaA * dd * dd);
            }
        } else {
            ppidx[tid] = -1;
        }
        __syncthreads();

        int cnt = min(CHUNK, npairs - base);
        // pass 0: feature f = tid (pidx = f>>5 is warp-uniform)
        {
            int f = tid;
            int pf = f >> 5, s = (f >> 3) & 3, t = f & 7;
            for (int q = 0; q < cnt; q++) {
                bool mt = (ppidx[q] == pf);
                float v = f1s[q * 9 + t] * f2s[q * 5 + s];
                acc0 += mt ? v : 0.0f;
            }
        }
        // pass 1: f = tid + 128
        {
            int f = tid + 128;
            int pf = f >> 5, s = (f >> 3) & 3, t = f & 7;
            for (int q = 0; q < cnt; q++) {
                bool mt = (ppidx[q] == pf);
                float v = f1s[q * 9 + t] * f2s[q * 5 + s];
                acc1 += mt ? v : 0.0f;
            }
        }
        // pass 2: f = tid + 256 (only tid < 64 -> f < 320), warps 0,1
        if (tid < ANG_FEAT - 256) {
            int f = tid + 256;
            int pf = f >> 5, s = (f >> 3) & 3, t = f & 7;
            for (int q = 0; q < cnt; q++) {
                bool mt = (ppidx[q] == pf);
                float v = f1s[q * 9 + t] * f2s[q * 5 + s];
                acc2 += mt ? v : 0.0f;
            }
        }
    }
    __syncthreads();

    // ---- write out ----
    float* o = out + ((size_t)m * NA + i) * AEV_LEN;
    if (tid < RAD_FEAT) o[tid] = radout[tid];
    o[RAD_FEAT + tid] = acc0;
    o[RAD_FEAT + 128 + tid] = acc1;
    if (tid < ANG_FEAT - 256) o[RAD_FEAT + 256 + tid] = acc2;
}

extern "C" void kernel_launch(void* const* d_in, const int* in_sizes, int n_in,
                              void* d_out, int out_size) {
    const float* coords = (const float*)d_in[0];
    const float* EtaR   = (const float*)d_in[1];
    const float* ShfR   = (const float*)d_in[2];
    const float* EtaA   = (const float*)d_in[3];
    const float* Zeta   = (const float*)d_in[4];
    const float* ShfA   = (const float*)d_in[5];
    const float* ShfZ   = (const float*)d_in[6];
    const int*   spec   = (const int*)d_in[7];
    float* out = (float*)d_out;

    int MA = in_sizes[7];
    int M = MA / NA;

    dim3 grid(NA, M);
    aev_kernel<<<grid, 128>>>(coords, EtaR, ShfR, EtaA, Zeta, ShfA, ShfZ, spec, out);
}

// round 4
// speedup vs baseline: 5.9015x; 1.2855x over previous
#include <cuda_runtime.h>
#include <math.h>

#define NA 48
#define NS 4
#define NSHFR 16
#define NSHFA 4
#define NSHFZ 8
#define RAD_FEAT (NS * NSHFR)                     // 64
#define ANG_SUB (NSHFA * NSHFZ)                   // 32
#define NPAIRS_SP (NS * (NS + 1) / 2)             // 10
#define ANG_FEAT (NPAIRS_SP * ANG_SUB)            // 320
#define AEV_LEN (RAD_FEAT + ANG_FEAT)             // 384
#define RCR_F 5.2f
#define RCA_F 3.5f
#define PI_F 3.14159265358979323846f
#define CHUNK 128

__device__ __forceinline__ int triu_idx(int a, int b) {
    int lo = min(a, b), hi = max(a, b);
    return lo * NS - (lo * (lo - 1)) / 2 + (hi - lo);
}

__device__ __forceinline__ float pow_zeta(float x, float zeta, bool z32) {
    if (z32) {
        float y = x * x;  // ^2
        y = y * y;        // ^4
        y = y * y;        // ^8
        y = y * y;        // ^16
        return y * y;     // ^32
    }
    return __powf(x, zeta);
}

__global__ __launch_bounds__(128, 8)
void aev_kernel(const float* __restrict__ coords,   // (M, A, 3)
                const float* __restrict__ gEtaR,
                const float* __restrict__ gShfR,    // (16,)
                const float* __restrict__ gEtaA,
                const float* __restrict__ gZeta,
                const float* __restrict__ gShfA,    // (4,)
                const float* __restrict__ gShfZ,    // (8,)
                const int*   __restrict__ species,  // (M, A)
                float* __restrict__ out)            // (M, A, 384)
{
    const int i = blockIdx.x;
    const int m = blockIdx.y;
    const int tid = threadIdx.x;
    const int lane = tid & 31;
    const int wid = tid >> 5;
    const unsigned ltm = (1u << lane) - 1u;

    __shared__ float sx[NA], sy[NA], sz[NA];
    __shared__ int   ssp[NA];
    __shared__ float shfr[NSHFR], shfa[NSHFA];
    __shared__ float cshfz[NSHFZ], sshfz[NSHFZ];
    __shared__ float s_etaR, s_etaA, s_zeta;
    // radial list, sorted by species
    __shared__ float dR[NA], qfcR[NA];
    __shared__ int   cntRspw[4][NS];       // per-warp per-species counts
    __shared__ int   rstart[NS + 1];       // species bucket starts
    // angular list (ballot order)
    __shared__ float avx[NA], avy[NA], avz[NA], ad[NA], afc[NA];
    __shared__ int   asp[NA];
    __shared__ int   wcntA[4];
    // per-chunk pair data
    __shared__ float f1s[CHUNK * 9];       // padded stride 9
    __shared__ float f2s[CHUNK * 5];       // padded stride 5
    __shared__ int   cntPw[4][NPAIRS_SP];  // per-warp per-pidx counts
    __shared__ int   pstart[NPAIRS_SP + 1];
    __shared__ int   order[CHUNK];         // pair slots sorted by pidx
    __shared__ float radout[RAD_FEAT];

    // ---- phase 0: load ----
    if (tid < NA) {
        const float* c = coords + ((size_t)m * NA + tid) * 3;
        sx[tid] = c[0];
        sy[tid] = c[1];
        sz[tid] = c[2];
        ssp[tid] = species[(size_t)m * NA + tid];
    }
    if (tid < NSHFR) shfr[tid] = gShfR[tid];
    if (tid < NSHFA) shfa[tid] = gShfA[tid];
    if (tid < NSHFZ) {
        float z = gShfZ[tid];
        cshfz[tid] = cosf(z);
        sshfz[tid] = sinf(z);
    }
    if (tid == 0) {
        s_etaR = gEtaR[0];
        s_etaA = gEtaA[0];
        s_zeta = gZeta[0];
    }
    if (tid < 16) ((int*)cntRspw)[tid] = 0;
    if (tid < 4) wcntA[tid] = 0;
    __syncthreads();

    const float cx = sx[i], cy = sy[i], cz = sz[i];
    const float etaR = s_etaR, etaA = s_etaA, zeta = s_zeta;
    const bool z32 = (zeta == 32.0f);

    // ---- phase 1: deterministic compaction ----
    {
        int j = tid;
        float dx = 0.f, dy = 0.f, dz = 0.f, d = 1e9f;
        bool valid = (j < NA) && (j != i);
        int sp = 0;
        if (valid) {
            dx = sx[j] - cx;
            dy = sy[j] - cy;
            dz = sz[j] - cz;
            d = sqrtf(dx * dx + dy * dy + dz * dz);
            sp = ssp[j];
        }
        bool inR = valid && (d <= RCR_F);
        bool inA = valid && (d <= RCA_F);
        unsigned ballR = __ballot_sync(0xffffffffu, inR);
        unsigned ballA = __ballot_sync(0xffffffffu, inA);

        // radial: group by species within warp
        unsigned mspR = __match_any_sync(0xffffffffu, inR ? sp : (NS + lane)) & ballR;
        int rankR = __popc(mspR & ltm);
        if (inR && (lane == (__ffs(mspR) - 1)))
            cntRspw[wid][sp] = __popc(mspR);

        // angular: plain ballot order
        int rankA = __popc(ballA & ltm);
        if (lane == 0) wcntA[wid] = __popc(ballA);
        __syncthreads();

        // species bucket starts (radial)
        if (tid <= NS) {
            int acc = 0;
            for (int s = 0; s < tid; s++)
                acc += cntRspw[0][s] + cntRspw[1][s] + cntRspw[2][s] + cntRspw[3][s];
            rstart[tid] = acc;
        }
        __syncthreads();

        if (inR) {
            int off = rstart[sp];
            for (int w = 0; w < wid; w++) off += cntRspw[w][sp];
            off += rankR;
            dR[off] = d;
            qfcR[off] = 0.25f * (0.5f * __cosf(d * (PI_F / RCR_F)) + 0.5f);
        }
        if (inA) {
            int off = rankA;
            for (int w = 0; w < wid; w++) off += wcntA[w];
            avx[off] = dx; avy[off] = dy; avz[off] = dz;
            ad[off] = d;
            afc[off] = 0.5f * __cosf(d * (PI_F / RCA_F)) + 0.5f;
            asp[off] = sp;
        }
    }
    __syncthreads();
    const int nA = wcntA[0] + wcntA[1] + wcntA[2] + wcntA[3];

    // ---- phase 2: radial, feature-parallel over species buckets ----
    if (tid < RAD_FEAT) {
        int sp = tid >> 4;
        float sk = shfr[tid & 15];
        float acc = 0.0f;
        int jb = rstart[sp], je = rstart[sp + 1];
        for (int j = jb; j < je; j++) {
            float t = dR[j] - sk;
            acc += qfcR[j] * __expf(-etaR * t * t);
        }
        radout[tid] = acc;
    }

    // ---- phase 3: angular pairs, chunked, bucket-sorted by pidx ----
    const int npairs = nA * (nA - 1) / 2;
    float acc0 = 0.f, acc1 = 0.f, acc2 = 0.f;

    for (int base = 0; base < npairs; base += CHUNK) {
        int p = base + tid;
        __syncthreads();   // protect previous chunk reads before overwrite
        if (tid < 4 * NPAIRS_SP) ((int*)cntPw)[tid] = 0;
        __syncthreads();

        int pidx = 32 + lane;  // sentinel (unique per lane, never matches real)
        if (p < npairs) {
            int a = 0, rem = p;
            while (rem >= nA - 1 - a) { rem -= nA - 1 - a; a++; }
            int b = a + 1 + rem;

            float d1 = ad[a], d2 = ad[b];
            float dot = avx[a] * avx[b] + avy[a] * avy[b] + avz[a] * avz[b];
            float cosv = 0.95f * __fdividef(dot, fmaxf(d1, 1e-8f) * fmaxf(d2, 1e-8f));
            float sinv = sqrtf(fmaxf(1.0f - cosv * cosv, 0.0f));
            float dm = 0.5f * (d1 + d2);
            float fcj2 = 2.0f * afc[a] * afc[b];
            pidx = triu_idx(asp[a], asp[b]);

            #pragma unroll
            for (int t = 0; t < NSHFZ; t++) {
                float c = cosv * cshfz[t] + sinv * sshfz[t];
                float bse = 0.5f * (1.0f + c);
                f1s[tid * 9 + t] = pow_zeta(bse, zeta, z32) * fcj2;
            }
            #pragma unroll
            for (int s = 0; s < NSHFA; s++) {
                float dd = dm - shfa[s];
                f2s[tid * 5 + s] = __expf(-etaA * dd * dd);
            }
        }

        // deterministic counting sort of pair slots by pidx
        unsigned msk = __match_any_sync(0xffffffffu, pidx);
        int rank = __popc(msk & ltm);
        bool valid = (pidx < NPAIRS_SP);
        if (valid && (lane == (__ffs(msk) - 1)))
            cntPw[wid][pidx] = __popc(msk);
        __syncthreads();

        if (tid <= NPAIRS_SP) {
            int acc = 0;
            for (int s = 0; s < tid; s++)
                acc += cntPw[0][s] + cntPw[1][s] + cntPw[2][s] + cntPw[3][s];
            pstart[tid] = acc;
        }
        __syncthreads();

        if (valid) {
            int off = pstart[pidx];
            for (int w = 0; w < wid; w++) off += cntPw[w][pidx];
            off += rank;
            order[off] = tid;
        }
        __syncthreads();

        // feature accumulation: each warp scans only its pidx bucket
        {
            int f = tid;                       // pf = wid (0..3)
            int pf = f >> 5, s = (f >> 3) & 3, t = f & 7;
            int qb = pstart[pf], qe = pstart[pf + 1];
            for (int q = qb; q < qe; q++) {
                int pid = order[q];
                acc0 += f1s[pid * 9 + t] * f2s[pid * 5 + s];
            }
        }
        {
            int f = tid + 128;                 // pf = 4 + wid
            int pf = f >> 5, s = (f >> 3) & 3, t = f & 7;
            int qb = pstart[pf], qe = pstart[pf + 1];
            for (int q = qb; q < qe; q++) {
                int pid = order[q];
                acc1 += f1s[pid * 9 + t] * f2s[pid * 5 + s];
            }
        }
        if (tid < ANG_FEAT - 256) {            // pf = 8 + wid (warps 0,1)
            int f = tid + 256;
            int pf = f >> 5, s = (f >> 3) & 3, t = f & 7;
            int qb = pstart[pf], qe = pstart[pf + 1];
            for (int q = qb; q < qe; q++) {
                int pid = order[q];
                acc2 += f1s[pid * 9 + t] * f2s[pid * 5 + s];
            }
        }
    }
    __syncthreads();

    // ---- write out ----
    float* o = out + ((size_t)m * NA + i) * AEV_LEN;
    if (tid < RAD_FEAT) o[tid] = radout[tid];
    o[RAD_FEAT + tid] = acc0;
    o[RAD_FEAT + 128 + tid] = acc1;
    if (tid < ANG_FEAT - 256) o[RAD_FEAT + 256 + tid] = acc2;
}

extern "C" void kernel_launch(void* const* d_in, const int* in_sizes, int n_in,
                              void* d_out, int out_size) {
    const float* coords = (const float*)d_in[0];
    const float* EtaR   = (const float*)d_in[1];
    const float* ShfR   = (const float*)d_in[2];
    const float* EtaA   = (const float*)d_in[3];
    const float* Zeta   = (const float*)d_in[4];
    const float* ShfA   = (const float*)d_in[5];
    const float* ShfZ   = (const float*)d_in[6];
    const int*   spec   = (const int*)d_in[7];
    float* out = (float*)d_out;

    int MA = in_sizes[7];
    int M = MA / NA;

    dim3 grid(NA, M);
    aev_kernel<<<grid, 128>>>(coords, EtaR, ShfR, EtaA, Zeta, ShfA, ShfZ, spec, out);
}

// round 5
// speedup vs baseline: 6.7078x; 1.1366x over previous
#include <cuda_runtime.h>
#include <math.h>

#define NA 48
#define NS 4
#define NSHFR 16
#define NSHFA 4
#define NSHFZ 8
#define RAD_FEAT (NS * NSHFR)                     // 64
#define ANG_SUB (NSHFA * NSHFZ)                   // 32
#define NPAIRS_SP (NS * (NS + 1) / 2)             // 10
#define ANG_FEAT (NPAIRS_SP * ANG_SUB)            // 320
#define AEV_LEN (RAD_FEAT + ANG_FEAT)             // 384
#define RCR_F 5.2f
#define RCA_F 3.5f
#define PI_F 3.14159265358979323846f
#define NTHR 256
#define NWARP 8
#define CHUNK 256

__device__ __forceinline__ int triu_idx(int a, int b) {
    int lo = min(a, b), hi = max(a, b);
    return lo * NS - (lo * (lo - 1)) / 2 + (hi - lo);
}

__device__ __forceinline__ float pow_zeta(float x, float zeta, bool z32) {
    if (z32) {
        float y = x * x;  // ^2
        y = y * y;        // ^4
        y = y * y;        // ^8
        y = y * y;        // ^16
        return y * y;     // ^32
    }
    return __powf(x, zeta);
}

__global__ __launch_bounds__(NTHR)
void aev_kernel(const float* __restrict__ coords,   // (M, A, 3)
                const float* __restrict__ gEtaR,
                const float* __restrict__ gShfR,    // (16,)
                const float* __restrict__ gEtaA,
                const float* __restrict__ gZeta,
                const float* __restrict__ gShfA,    // (4,)
                const float* __restrict__ gShfZ,    // (8,)
                const int*   __restrict__ species,  // (M, A)
                float* __restrict__ out)            // (M, A, 384)
{
    const int i = blockIdx.x;
    const int m = blockIdx.y;
    const int tid = threadIdx.x;
    const int lane = tid & 31;
    const int wid = tid >> 5;
    const unsigned ltm = (1u << lane) - 1u;

    __shared__ float sx[NA], sy[NA], sz[NA];
    __shared__ int   ssp[NA];
    __shared__ float shfr[NSHFR], shfa[NSHFA];
    __shared__ float cshfz[NSHFZ], sshfz[NSHFZ];
    __shared__ float s_etaR, s_etaA, s_zeta;
    // radial list, sorted by species
    __shared__ float dR[NA], qfcR[NA];
    __shared__ int   cntRspw[2][NS];
    __shared__ int   rstart[NS + 1];
    // angular list (ballot order)
    __shared__ float avx[NA], avy[NA], avz[NA], ad[NA], afc[NA];
    __shared__ int   asp[NA];
    __shared__ int   wcntA[2];
    // per-chunk pair data (stored pre-sorted by pidx)
    __shared__ float f1s[CHUNK * 9];           // padded stride 9
    __shared__ float f2s[CHUNK * 5];           // padded stride 5
    __shared__ int   cntPw[NWARP][NPAIRS_SP];
    __shared__ int   pstart[NPAIRS_SP + 1];
    __shared__ float radout[RAD_FEAT];

    // ---- phase 0: load ----
    if (tid < NA) {
        const float* c = coords + ((size_t)m * NA + tid) * 3;
        sx[tid] = c[0];
        sy[tid] = c[1];
        sz[tid] = c[2];
        ssp[tid] = species[(size_t)m * NA + tid];
    }
    if (tid < NSHFR) shfr[tid] = gShfR[tid];
    if (tid < NSHFA) shfa[tid] = gShfA[tid];
    if (tid < NSHFZ) {
        float z = gShfZ[tid];
        cshfz[tid] = cosf(z);
        sshfz[tid] = sinf(z);
    }
    if (tid == 0) {
        s_etaR = gEtaR[0];
        s_etaA = gEtaA[0];
        s_zeta = gZeta[0];
    }
    if (tid < 2 * NS) ((int*)cntRspw)[tid] = 0;
    if (tid < 2) wcntA[tid] = 0;
    __syncthreads();

    const float cx = sx[i], cy = sy[i], cz = sz[i];
    const float etaR = s_etaR, etaA = s_etaA, zeta = s_zeta;
    const bool z32 = (zeta == 32.0f);

    // ---- phase 1: deterministic compaction (warps 0,1 cover j = 0..47) ----
    if (wid < 2) {
        int j = tid;
        float dx = 0.f, dy = 0.f, dz = 0.f, d = 1e9f;
        bool valid = (j < NA) && (j != i);
        int sp = 0;
        if (valid) {
            dx = sx[j] - cx;
            dy = sy[j] - cy;
            dz = sz[j] - cz;
            d = sqrtf(dx * dx + dy * dy + dz * dz);
            sp = ssp[j];
        }
        bool inR = valid && (d <= RCR_F);
        bool inA = valid && (d <= RCA_F);
        unsigned ballR = __ballot_sync(0xffffffffu, inR);
        unsigned ballA = __ballot_sync(0xffffffffu, inA);

        unsigned mspR = __match_any_sync(0xffffffffu, inR ? sp : (NS + lane)) & ballR;
        int rankR = __popc(mspR & ltm);
        if (inR && (lane == (__ffs(mspR) - 1)))
            cntRspw[wid][sp] = __popc(mspR);

        int rankA = __popc(ballA & ltm);
        if (lane == 0) wcntA[wid] = __popc(ballA);
        __syncthreads();

        if (tid <= NS) {
            int acc = 0;
            for (int s = 0; s < tid; s++)
                acc += cntRspw[0][s] + cntRspw[1][s];
            rstart[tid] = acc;
        }
        __syncthreads();

        if (inR) {
            int off = rstart[sp] + rankR;
            if (wid == 1) off += cntRspw[0][sp];
            dR[off] = d;
            qfcR[off] = 0.25f * (0.5f * __cosf(d * (PI_F / RCR_F)) + 0.5f);
        }
        if (inA) {
            int off = rankA;
            if (wid == 1) off += wcntA[0];
            avx[off] = dx; avy[off] = dy; avz[off] = dz;
            ad[off] = d;
            afc[off] = 0.5f * __cosf(d * (PI_F / RCA_F)) + 0.5f;
            asp[off] = sp;
        }
    } else {
        __syncthreads();
        __syncthreads();
    }
    __syncthreads();
    const int nA = wcntA[0] + wcntA[1];

    // ---- phase 2: radial, feature-parallel over species buckets ----
    if (tid < RAD_FEAT) {
        int sp = tid >> 4;
        float sk = shfr[tid & 15];
        float acc = 0.0f;
        int jb = rstart[sp], je = rstart[sp + 1];
        for (int j = jb; j < je; j++) {
            float t = dR[j] - sk;
            acc += qfcR[j] * __expf(-etaR * t * t);
        }
        radout[tid] = acc;
    }

    // ---- phase 3: angular pairs, chunked, pre-sorted by pidx ----
    const int npairs = nA * (nA - 1) / 2;
    float acc0 = 0.f, acc1 = 0.f;

    for (int base = 0; base < npairs; base += CHUNK) {
        int p = base + tid;
        bool pvalid = (p < npairs);
        __syncthreads();   // previous chunk's scan complete before overwriting

        int a = 0, b = 0, pidx = NPAIRS_SP + lane;  // sentinel distinct per lane
        if (pvalid) {
            // closed-form decode p -> (a,b), a < b, with rounding fix-up
            float fn = (float)nA;
            float tt = 2.0f * fn - 1.0f;
            a = (int)(0.5f * (tt - sqrtf(fmaxf(tt * tt - 8.0f * (float)p, 0.0f))));
            while (a > 0 && p < a * nA - (a * (a + 1)) / 2) a--;
            while (p >= (a + 1) * nA - ((a + 1) * (a + 2)) / 2) a++;
            b = p - (a * nA - (a * (a + 1)) / 2) + a + 1;
            pidx = triu_idx(asp[a], asp[b]);
        }

        // per-warp per-bucket histogram via ballots; rank via match
        unsigned msk = __match_any_sync(0xffffffffu, pidx);
        int rank = __popc(msk & ltm);
        #pragma unroll
        for (int k = 0; k < NPAIRS_SP; k++) {
            unsigned bk = __ballot_sync(0xffffffffu, pidx == k);
            if (lane == k) cntPw[wid][k] = __popc(bk);
        }
        __syncthreads();

        if (tid <= NPAIRS_SP) {
            int acc = 0;
            for (int s = 0; s < tid; s++) {
                int t = 0;
                #pragma unroll
                for (int w = 0; w < NWARP; w++) t += cntPw[w][s];
                acc += t;
            }
            pstart[tid] = acc;
        }
        __syncthreads();

        if (pvalid) {
            int slot = pstart[pidx] + rank;
            for (int w = 0; w < wid; w++) slot += cntPw[w][pidx];

            float d1 = ad[a], d2 = ad[b];
            float dot = avx[a] * avx[b] + avy[a] * avy[b] + avz[a] * avz[b];
            float cosv = 0.95f * __fdividef(dot, fmaxf(d1, 1e-8f) * fmaxf(d2, 1e-8f));
            float sinv = sqrtf(fmaxf(1.0f - cosv * cosv, 0.0f));
            float dm = 0.5f * (d1 + d2);
            float fcj2 = 2.0f * afc[a] * afc[b];

            #pragma unroll
            for (int t = 0; t < NSHFZ; t++) {
                float c = cosv * cshfz[t] + sinv * sshfz[t];
                float bse = 0.5f * (1.0f + c);
                f1s[slot * 9 + t] = pow_zeta(bse, zeta, z32) * fcj2;
            }
            #pragma unroll
            for (int s = 0; s < NSHFA; s++) {
                float dd = dm - shfa[s];
                f2s[slot * 5 + s] = __expf(-etaA * dd * dd);
            }
        }
        __syncthreads();

        // feature accumulation: warp w owns bucket w (pass 0), bucket 8+w (pass 1)
        {
            int s = (tid >> 3) & 3, t = tid & 7;
            int qb = pstart[wid], qe = pstart[wid + 1];
            for (int q = qb; q < qe; q++)
                acc0 += f1s[q * 9 + t] * f2s[q * 5 + s];
        }
        if (tid < ANG_FEAT - CHUNK) {   // tid < 64: buckets 8,9
            int pf = 8 + (tid >> 5), s = (tid >> 3) & 3, t = tid & 7;
            int qb = pstart[pf], qe = pstart[pf + 1];
            for (int q = qb; q < qe; q++)
                acc1 += f1s[q * 9 + t] * f2s[q * 5 + s];
        }
    }
    __syncthreads();

    // ---- write out ----
    float* o = out + ((size_t)m * NA + i) * AEV_LEN;
    if (tid < RAD_FEAT) o[tid] = radout[tid];
    o[RAD_FEAT + tid] = acc0;
    if (tid < ANG_FEAT - CHUNK) o[RAD_FEAT + CHUNK + tid] = acc1;
}

extern "C" void kernel_launch(void* const* d_in, const int* in_sizes, int n_in,
                              void* d_out, int out_size) {
    const float* coords = (const float*)d_in[0];
    const float* EtaR   = (const float*)d_in[1];
    const float* ShfR   = (const float*)d_in[2];
    const float* EtaA   = (const float*)d_in[3];
    const float* Zeta   = (const float*)d_in[4];
    const float* ShfA   = (const float*)d_in[5];
    const float* ShfZ   = (const float*)d_in[6];
    const int*   spec   = (const int*)d_in[7];
    float* out = (float*)d_out;

    int MA = in_sizes[7];
    int M = MA / NA;

    dim3 grid(NA, M);
    aev_kernel<<<grid, NTHR>>>(coords, EtaR, ShfR, EtaA, Zeta, ShfA, ShfZ, spec, out);
}

// round 8
// speedup vs baseline: 7.0700x; 1.0540x over previous
#include <cuda_runtime.h>
#include <math.h>

#define NA 48
#define NS 4
#define NSHFR 16
#define NSHFA 4
#define NSHFZ 8
#define RAD_FEAT (NS * NSHFR)                     // 64
#define ANG_SUB (NSHFA * NSHFZ)                   // 32
#define NPAIRS_SP (NS * (NS + 1) / 2)             // 10
#define ANG_FEAT (NPAIRS_SP * ANG_SUB)            // 320
#define AEV_LEN (RAD_FEAT + ANG_FEAT)             // 384
#define RCR_F 5.2f
#define RCA_F 3.5f
#define PI_F 3.14159265358979323846f
#define NTHR 256
#define NWARP 8
#define CHUNK 256

__device__ __forceinline__ int triu_idx(int a, int b) {
    int lo = min(a, b), hi = max(a, b);
    return lo * NS - (lo * (lo - 1)) / 2 + (hi - lo);
}

__device__ __forceinline__ float pow_zeta(float x, float zeta, bool z32) {
    if (z32) {
        float y = x * x;  // ^2
        y = y * y;        // ^4
        y = y * y;        // ^8
        y = y * y;        // ^16
        return y * y;     // ^32
    }
    return __powf(x, zeta);
}

__global__ __launch_bounds__(NTHR, 6)
void aev_kernel(const float* __restrict__ coords,   // (M, A, 3)
                const float* __restrict__ gEtaR,
                const float* __restrict__ gShfR,    // (16,)
                const float* __restrict__ gEtaA,
                const float* __restrict__ gZeta,
                const float* __restrict__ gShfA,    // (4,)
                const float* __restrict__ gShfZ,    // (8,)
                const int*   __restrict__ species,  // (M, A)
                float* __restrict__ out)            // (M, A, 384)
{
    const int i = blockIdx.x;
    const int m = blockIdx.y;
    const int tid = threadIdx.x;
    const int lane = tid & 31;
    const int wid = tid >> 5;
    const unsigned ltm = (1u << lane) - 1u;

    __shared__ float sx[NA], sy[NA], sz[NA];
    __shared__ int   ssp[NA];
    __shared__ float shfr[NSHFR], shfa[NSHFA];
    __shared__ float cshfz[NSHFZ], sshfz[NSHFZ];
    __shared__ float s_etaR, s_etaA, s_zeta;
    // radial list, sorted by species
    __shared__ float dR[NA], qfcR[NA];
    __shared__ int   cntRspw[2][NS];
    __shared__ int   rstart[NS + 1];
    // angular list (ballot order)
    __shared__ float avx[NA], avy[NA], avz[NA], ad[NA], afc[NA];
    __shared__ int   asp[NA];
    __shared__ int   wcntA[2];
    // per-chunk pair data (stored pre-sorted by pidx)
    __shared__ float f1s[CHUNK * 9];           // padded stride 9
    __shared__ float f2s[CHUNK * 5];           // padded stride 5
    __shared__ int   cntPw[NWARP][NPAIRS_SP];  // becomes exclusive warp-prefix
    __shared__ int   pstart[NPAIRS_SP + 1];
    __shared__ float radout[RAD_FEAT];

    // ---- phase 0: load ----
    if (tid < NA) {
        const float* c = coords + ((size_t)m * NA + tid) * 3;
        sx[tid] = c[0];
        sy[tid] = c[1];
        sz[tid] = c[2];
        ssp[tid] = species[(size_t)m * NA + tid];
    }
    if (tid < NSHFR) shfr[tid] = gShfR[tid];
    if (tid < NSHFA) shfa[tid] = gShfA[tid];
    if (tid < NSHFZ) {
        float z = gShfZ[tid];
        cshfz[tid] = cosf(z);
        sshfz[tid] = sinf(z);
    }
    if (tid == 0) {
        s_etaR = gEtaR[0];
        s_etaA = gEtaA[0];
        s_zeta = gZeta[0];
    }
    if (tid < 2 * NS) ((int*)cntRspw)[tid] = 0;
    if (tid < 2) wcntA[tid] = 0;
    __syncthreads();

    const float cx = sx[i], cy = sy[i], cz = sz[i];
    const float etaR = s_etaR, etaA = s_etaA, zeta = s_zeta;
    const bool z32 = (zeta == 32.0f);

    // ---- phase 1: deterministic compaction (warps 0,1 cover j = 0..47) ----
    if (wid < 2) {
        int j = tid;
        float dx = 0.f, dy = 0.f, dz = 0.f, d = 1e9f;
        bool valid = (j < NA) && (j != i);
        int sp = 0;
        if (valid) {
            dx = sx[j] - cx;
            dy = sy[j] - cy;
            dz = sz[j] - cz;
            d = sqrtf(dx * dx + dy * dy + dz * dz);
            sp = ssp[j];
        }
        bool inR = valid && (d <= RCR_F);
        bool inA = valid && (d <= RCA_F);
        unsigned ballR = __ballot_sync(0xffffffffu, inR);
        unsigned ballA = __ballot_sync(0xffffffffu, inA);

        unsigned mspR = __match_any_sync(0xffffffffu, inR ? sp : (NS + lane)) & ballR;
        int rankR = __popc(mspR & ltm);
        if (inR && (lane == (__ffs(mspR) - 1)))
            cntRspw[wid][sp] = __popc(mspR);

        int rankA = __popc(ballA & ltm);
        if (lane == 0) wcntA[wid] = __popc(ballA);
        __syncthreads();

        if (tid <= NS) {
            int acc = 0;
            for (int s = 0; s < tid; s++)
                acc += cntRspw[0][s] + cntRspw[1][s];
            rstart[tid] = acc;
        }
        __syncthreads();

        if (inR) {
            int off = rstart[sp] + rankR;
            if (wid == 1) off += cntRspw[0][sp];
            dR[off] = d;
            qfcR[off] = 0.25f * (0.5f * __cosf(d * (PI_F / RCR_F)) + 0.5f);
        }
        if (inA) {
            int off = rankA;
            if (wid == 1) off += wcntA[0];
            avx[off] = dx; avy[off] = dy; avz[off] = dz;
            ad[off] = d;
            afc[off] = 0.5f * __cosf(d * (PI_F / RCA_F)) + 0.5f;
            asp[off] = sp;
        }
    } else {
        __syncthreads();
        __syncthreads();
    }
    __syncthreads();
    const int nA = wcntA[0] + wcntA[1];

    // ---- phase 2: radial, feature-parallel over species buckets ----
    if (tid < RAD_FEAT) {
        int sp = tid >> 4;
        float sk = shfr[tid & 15];
        float acc = 0.0f;
        int jb = rstart[sp], je = rstart[sp + 1];
        for (int j = jb; j < je; j++) {
            float t = dR[j] - sk;
            acc += qfcR[j] * __expf(-etaR * t * t);
        }
        radout[tid] = acc;
    }

    // ---- phase 3: angular pairs, chunked, pre-sorted by pidx ----
    const int npairs = nA * (nA - 1) / 2;
    float acc0 = 0.f, acc1 = 0.f;

    for (int base = 0; base < npairs; base += CHUNK) {
        int p = base + tid;
        bool pvalid = (p < npairs);
        __syncthreads();   // previous chunk's scan complete before overwriting

        int a = 0, b = 0, pidx = NPAIRS_SP + lane;  // sentinel distinct per lane
        if (pvalid) {
            // closed-form decode p -> (a,b), a < b, with rounding fix-up
            float fn = (float)nA;
            float tt = 2.0f * fn - 1.0f;
            a = (int)(0.5f * (tt - sqrtf(fmaxf(tt * tt - 8.0f * (float)p, 0.0f))));
            while (a > 0 && p < a * nA - (a * (a + 1)) / 2) a--;
            while (p >= (a + 1) * nA - ((a + 1) * (a + 2)) / 2) a++;
            b = p - (a * nA - (a * (a + 1)) / 2) + a + 1;
            pidx = triu_idx(asp[a], asp[b]);
        }

        // per-warp per-bucket histogram via ballots; rank via match
        unsigned msk = __match_any_sync(0xffffffffu, pidx);
        int rank = __popc(msk & ltm);
        #pragma unroll
        for (int k = 0; k < NPAIRS_SP; k++) {
            unsigned bk = __ballot_sync(0xffffffffu, pidx == k);
            if (lane == k) cntPw[wid][k] = __popc(bk);
        }
        __syncthreads();

        // warp 0: in-place exclusive scan of cntPw over warps per bucket,
        // then shuffle-scan bucket totals -> pstart
        if (wid == 0) {
            int tot = 0;
            if (lane < NPAIRS_SP) {
                int acc = 0;
                #pragma unroll
                for (int w = 0; w < NWARP; w++) {
                    int c = cntPw[w][lane];
                    cntPw[w][lane] = acc;   // exclusive prefix across warps
                    acc += c;
                }
                tot = acc;
            }
            int scan = tot;
            #pragma unroll
            for (int o = 1; o < 16; o <<= 1) {
                int v = __shfl_up_sync(0xffffffffu, scan, o);
                if (lane >= o) scan += v;
            }
            if (lane < NPAIRS_SP) pstart[lane + 1] = scan;
            if (lane == 0) pstart[0] = 0;
        }
        __syncthreads();

        if (pvalid) {
            int slot = pstart[pidx] + cntPw[wid][pidx] + rank;

            float d1 = ad[a], d2 = ad[b];
            float dot = avx[a] * avx[b] + avy[a] * avy[b] + avz[a] * avz[b];
            float cosv = 0.95f * __fdividef(dot, fmaxf(d1, 1e-8f) * fmaxf(d2, 1e-8f));
            float sinv = sqrtf(fmaxf(1.0f - cosv * cosv, 0.0f));
            float dm = 0.5f * (d1 + d2);
            float fcj2 = 2.0f * afc[a] * afc[b];

            #pragma unroll
            for (int t = 0; t < NSHFZ; t++) {
                float c = cosv * cshfz[t] + sinv * sshfz[t];
                float bse = 0.5f * (1.0f + c);
                f1s[slot * 9 + t] = pow_zeta(bse, zeta, z32) * fcj2;
            }
            #pragma unroll
            for (int s = 0; s < NSHFA; s++) {
                float dd = dm - shfa[s];
                f2s[slot * 5 + s] = __expf(-etaA * dd * dd);
            }
        }
        __syncthreads();

        // feature accumulation: warp w owns bucket w (pass 0); buckets 8,9 -> warps 0,1
        {
            int s = (tid >> 3) & 3, t = tid & 7;
            int qb = pstart[wid], qe = pstart[wid + 1];
            for (int q = qb; q < qe; q++)
                acc0 += f1s[q * 9 + t] * f2s[q * 5 + s];
        }
        if (tid < ANG_FEAT - CHUNK) {   // tid < 64: buckets 8,9
            int pf = 8 + (tid >> 5), s = (tid >> 3) & 3, t = tid & 7;
            int qb = pstart[pf], qe = pstart[pf + 1];
            for (int q = qb; q < qe; q++)
                acc1 += f1s[q * 9 + t] * f2s[q * 5 + s];
        }
    }
    __syncthreads();

    // ---- write out ----
    float* o = out + ((size_t)m * NA + i) * AEV_LEN;
    if (tid < RAD_FEAT) o[tid] = radout[tid];
    o[RAD_FEAT + tid] = acc0;
    if (tid < ANG_FEAT - CHUNK) o[RAD_FEAT + CHUNK + tid] = acc1;
}

extern "C" void kernel_launch(void* const* d_in, const int* in_sizes, int n_in,
                              void* d_out, int out_size) {
    const float* coords = (const float*)d_in[0];
    const float* EtaR   = (const float*)d_in[1];
    const float* ShfR   = (const float*)d_in[2];
    const float* EtaA   = (const float*)d_in[3];
    const float* Zeta   = (const float*)d_in[4];
    const float* ShfA   = (const float*)d_in[5];
    const float* ShfZ   = (const float*)d_in[6];
    const int*   spec   = (const int*)d_in[7];
    float* out = (float*)d_out;

    int MA = in_sizes[7];
    int M = MA / NA;

    dim3 grid(NA, M);
    aev_kernel<<<grid, NTHR>>>(coords, EtaR, ShfR, EtaA, Zeta, ShfA, ShfZ, spec, out);
}